// round 14
// baseline (speedup 1.0000x reference)
#include <cuda_runtime.h>

#define BB   32
#define SS   1024
#define DD   256
#define L1   1030      // conv1 output length
#define KSEL 515       // k-max k for layer 1
#define CH1  768       // channels after fold1 (128 groups x 6)
#define L2IN 515
#define L2   519       // conv2 output length
#define CH2  896       // channels after fold2 (64 x 14)
#define CC   1000
#define KF   3584
#define KSPLIT 56      // fc k-splits of 64

// scratch (static device globals; no runtime allocation)
__device__ float g_h0[BB * DD * SS];         // (b, d, s) embedded+transposed
__device__ float g_h1[BB * CH1 * KSEL];      // (b, c1, pos) after kmax+tanh
__device__ float g_h3[BB * CH2 * 4];         // (b, c2, 4) after top4+tanh
__device__ float g_fcp[KSPLIT * BB * CC];    // fc partial sums

__device__ __forceinline__ unsigned int f2key(float v) {
    unsigned int u = __float_as_uint(v);
    return u ^ ((u & 0x80000000u) ? 0xFFFFFFFFu : 0x80000000u);
}
__device__ __forceinline__ float key2f(unsigned int k) {
    unsigned int u = k ^ ((k & 0x80000000u) ? 0x80000000u : 0xFFFFFFFFu);
    return __uint_as_float(u);
}
__device__ __forceinline__ float fast_tanh(float x) {
    float ax = fabsf(x);
    float t = __expf(-2.f * ax);
    float r = __fdividef(1.f - t, 1.f + t);
    return copysignf(r, x);
}

// packed f32x2 helpers (sm_103a FFMA2 path)
__device__ __forceinline__ unsigned long long pk2(float lo, float hi) {
    unsigned long long r;
    asm("mov.b64 %0, {%1,%2};" : "=l"(r) : "f"(lo), "f"(hi));
    return r;
}
__device__ __forceinline__ void upk2(unsigned long long v, float& lo, float& hi) {
    asm("mov.b64 {%0,%1}, %2;" : "=f"(lo), "=f"(hi) : "l"(v));
}
__device__ __forceinline__ void fma2(unsigned long long& d, unsigned long long a,
                                     unsigned long long b) {
    asm("fma.rn.f32x2 %0, %1, %2, %3;" : "=l"(d) : "l"(a), "l"(b), "l"(d));
}

__device__ __forceinline__ int wexscan(int v, int lane) {
    int s = v;
#pragma unroll
    for (int o = 1; o < 32; o <<= 1) {
        int n = __shfl_up_sync(0xffffffffu, s, o);
        if (lane >= o) s += n;
    }
    return s - v;
}
__device__ __forceinline__ unsigned wredAnd(unsigned v) {
#pragma unroll
    for (int o = 16; o; o >>= 1) v &= __shfl_xor_sync(0xffffffffu, v, o);
    return v;
}
__device__ __forceinline__ unsigned wredOr(unsigned v) {
#pragma unroll
    for (int o = 16; o; o >>= 1) v |= __shfl_xor_sync(0xffffffffu, v, o);
    return v;
}

// ---------------------------------------------------------------------------
// Kernel 1: embedding gather + transpose  (B,S) tokens -> g_h0 (b, d, s)
// ---------------------------------------------------------------------------
__global__ __launch_bounds__(256) void k_gather(const int* __restrict__ x,
                                                const float* __restrict__ emb) {
    __shared__ float tile[32][257];
    __shared__ int toks[32];
    int b = blockIdx.y;
    int sBase = blockIdx.x * 32;
    int t = threadIdx.x;
    if (t < 32) toks[t] = x[b * SS + sBase + t];
    __syncthreads();
    int rowB = t >> 6;         // 0..3
    int col4 = (t & 63) * 4;   // 0..252
#pragma unroll
    for (int i = 0; i < 8; i++) {
        int row = rowB + i * 4;
        const float4 v = *(const float4*)&emb[(size_t)(unsigned)toks[row] * DD + col4];
        tile[row][col4] = v.x; tile[row][col4 + 1] = v.y;
        tile[row][col4 + 2] = v.z; tile[row][col4 + 3] = v.w;
    }
    __syncthreads();
    int sl = t & 31, wg = t >> 5;
#pragma unroll 4
    for (int r = 0; r < 32; r++) {
        int d = wg * 32 + r;
        g_h0[((b * DD + d) << 10) + sBase + sl] = tile[sl][d];
    }
}

// ---------------------------------------------------------------------------
// Kernel 2: conv1(K=7, depthwise, packed FMA2) + fold + order-preserving
//           k-max(515 of 1030) + tanh.  One WARP per selection row.
//           Sign partition fused into conv pass (two-sided write) kills the
//           first (largest) search round; then AND/OR bit-skipping radix
//           partition; stable compaction from register key cache.
//           Launched in 8 grid slices (roff) so ncu -s5 -c1 captures it.
// ---------------------------------------------------------------------------
__global__ __launch_bounds__(192) void k_conv1(const float* __restrict__ w1,
                                               const float* __restrict__ b1,
                                               int roff) {
    __shared__ unsigned long long e01[1064];   // packed {ch0, ch1}
    __shared__ unsigned int act[6][L1];        // per-warp active buffer

    int r = roff + blockIdx.x, b = blockIdx.y;
    int t = threadIdx.x;
    int f = t >> 5, lane = t & 31;
    unsigned lt = (1u << lane) - 1u;

    const float* s0 = g_h0 + ((b * DD + 2 * r) << 10);
    for (int m = t; m < 1064; m += 192) {
        float v0 = 0.f, v1 = 0.f;
        if (m >= 6 && m < 6 + SS) { v0 = s0[m - 6]; v1 = s0[SS + m - 6]; }
        e01[m] = pk2(v0, v1);
    }
    __syncthreads();

    int o0 = (2 * r) * 6 + f, o1 = (2 * r + 1) * 6 + f;
    float bias = b1[o0] + b1[o1];
    unsigned long long W[7];
#pragma unroll
    for (int k = 0; k < 7; k++) W[k] = pk2(w1[o0 * 7 + k], w1[o1 * 7 + k]);

    int base = lane * 33;                 // lane-contiguous chunk (stable order)
    unsigned int* ab = act[f];

    // ---- conv pass: keys to registers + two-sided sign partition in act ----
    unsigned int key[33];
    unsigned long long P[7];
#pragma unroll
    for (int k = 0; k < 7; k++) P[k] = e01[base + k];
    unsigned andP = 0xFFFFFFFFu, orP = 0u, andN = 0xFFFFFFFFu, orN = 0u;
    int frontBase = 0, backBase = 0;
#pragma unroll
    for (int j = 0; j < 33; j++) {
        unsigned long long acc = pk2(bias, 0.f);
#pragma unroll
        for (int k = 0; k < 7; k++) fma2(acc, P[k], W[k]);
        float lo, hi; upk2(acc, lo, hi);
        unsigned kk = 0u;
        int valid = (j < 7) || (lane < 31);   // base+j < L1
        unsigned vm = (j < 7) ? 0xFFFFFFFFu : 0x7FFFFFFFu;
        if (valid) kk = f2key(lo + hi);
        key[j] = kk;
        int hibit = valid && (kk >> 31);
        unsigned balH = __ballot_sync(0xffffffffu, hibit);
        unsigned balL = vm & ~balH;
        if (hibit) {
            ab[frontBase + __popc(balH & lt)] = kk;
            andP &= kk; orP |= kk;
        } else if (valid) {
            ab[1029 - (backBase + __popc(balL & lt))] = kk;
            andN &= kk; orN |= kk;
        }
        frontBase += __popc(balH);
        backBase += __popc(balL);
#pragma unroll
        for (int k = 0; k < 6; k++) P[k] = P[k + 1];
        P[6] = e01[base + j + 7];
    }
    __syncwarp();

    unsigned aP = wredAnd(andP), oP = wredOr(orP);
    unsigned aN = wredAnd(andN), oN = wredOr(orN);

    // choose the side containing the 515th element
    int g, A, rs;
    unsigned andA, orA;
    if (frontBase >= KSEL) { g = 0; A = frontBase; rs = 0; andA = aP; orA = oP; }
    else { g = frontBase; A = 1030 - frontBase; rs = 1030 - A; andA = aN; orA = oN; }

    // ---- bit-skipping radix threshold search (warp-local) ----
#pragma unroll 1
    for (int it = 0; it < 32; it++) {
        unsigned diff = andA ^ orA;
        if (diff == 0u) break;
        int bpos = 31 - __clz(diff);
        int chunks = (A + 31) >> 5;
        int c = 0;
#pragma unroll 1
        for (int ch = 0; ch < chunks; ch++) {
            int ix = (ch << 5) + lane;
            unsigned v = (ix < A) ? ab[rs + ix] : 0u;
            int pr = (ix < A) && ((v >> bpos) & 1u);
            c += __popc(__ballot_sync(0xffffffffu, pr));
        }
        int keepHigh = (g + c >= KSEL);
        unsigned na = 0xFFFFFFFFu, no = 0u;
        int nw = 0;
#pragma unroll 1
        for (int ch = 0; ch < chunks; ch++) {
            int ix = (ch << 5) + lane;
            unsigned v = (ix < A) ? ab[rs + ix] : 0u;
            int keep = (ix < A) && ((int)((v >> bpos) & 1u) == keepHigh);
            unsigned bal = __ballot_sync(0xffffffffu, keep);
            if (keep) {
                ab[rs + nw + __popc(bal & lt)] = v;
                na &= v; no |= v;
            }
            nw += __popc(bal);
        }
        if (!keepHigh) g += c;
        A = nw;
        andA = wredAnd(na);
        orA = wredOr(no);
        __syncwarp();
    }
    unsigned T = andA;
    int limit = KSEL - g;                 // equal-to-T elements to keep

    // ---- stable compaction from registers (original position order) ----
    int cntG = 0, cntE = 0;
#pragma unroll
    for (int j = 0; j < 33; j++) {
        int valid = (j < 7) || (lane < 31);
        cntG += valid && (key[j] > T);
        cntE += valid && (key[j] == T);
    }
    int eqBefore = wexscan(cntE, lane);
    int eqTake = limit - eqBefore;
    if (eqTake < 0) eqTake = 0;
    if (eqTake > cntE) eqTake = cntE;
    int keepCnt = cntG + eqTake;
    int wrBase = wexscan(keepCnt, lane);

    float* orow = g_h1 + (size_t)(b * CH1 + r * 6 + f) * KSEL;
    int eq = eqBefore, wr = wrBase;
#pragma unroll
    for (int j = 0; j < 33; j++) {
        int valid = (j < 7) || (lane < 31);
        if (valid) {
            int isG = key[j] > T;
            int isE = key[j] == T;
            int kept = isG || (isE && (eq < limit));
            eq += isE;
            if (kept) { orow[wr] = fast_tanh(key2f(key[j])); wr++; }
        }
    }
}

// top-4 merge of two descending sorted-4 u64 lists
#define MERGE4(a0, a1, a2, a3, q0, q1, q2, q3)                                  \
    {                                                                           \
        unsigned long long m0 = (a0) > (q3) ? (a0) : (q3);                      \
        unsigned long long m1 = (a1) > (q2) ? (a1) : (q2);                      \
        unsigned long long m2 = (a2) > (q1) ? (a2) : (q1);                      \
        unsigned long long m3 = (a3) > (q0) ? (a3) : (q0);                      \
        unsigned long long d0 = m0 > m2 ? m0 : m2, d2 = m0 > m2 ? m2 : m0;      \
        unsigned long long d1 = m1 > m3 ? m1 : m3, d3 = m1 > m3 ? m3 : m1;      \
        a0 = d0 > d1 ? d0 : d1; a1 = d0 > d1 ? d1 : d0;                         \
        a2 = d2 > d3 ? d2 : d3; a3 = d2 > d3 ? d3 : d2;                         \
    }
#define INS4(e)                                                                 \
    {                                                                           \
        if ((e) > s0)      { s3 = s2; s2 = s1; s1 = s0; s0 = (e); }             \
        else if ((e) > s1) { s3 = s2; s2 = s1; s1 = (e); }                      \
        else if ((e) > s2) { s3 = s2; s2 = (e); }                               \
        else if ((e) > s3) { s3 = (e); }                                        \
    }

// ---------------------------------------------------------------------------
// Kernel 3: conv2(K=5, grouped 6->14, packed FMA2 over folded groups) +
//           order-preserving top-4 + tanh. One WARP per filter.
//           (identical to the measured 411.7us version)
// ---------------------------------------------------------------------------
__global__ __launch_bounds__(448) void k_conv2(const float* __restrict__ w2,
                                               const float* __restrict__ b2) {
    __shared__ float in[12][552];
    __shared__ float wsh[840];
    __shared__ float bsh[14];

    int r2 = blockIdx.x, b = blockIdx.y;
    int t = threadIdx.x, lane = t & 31, f = t >> 5;

    const float* src = g_h1 + (size_t)(b * CH1 + r2 * 12) * KSEL;
    for (int idx = t; idx < 12 * 552; idx += 448) {
        int row = idx / 552, m = idx - row * 552;
        float v = 0.f;
        if (m >= 4 && m < 4 + L2IN) v = src[row * KSEL + m - 4];
        in[row][m] = v;
    }
    for (int idx = t; idx < 840; idx += 448) {
        int fr = idx / 30, rem = idx - fr * 30;
        int gg = 2 * r2 + (fr >= 14);
        int ff = (fr >= 14) ? fr - 14 : fr;
        wsh[idx] = w2[(gg * 14 + ff) * 30 + rem];
    }
    if (t < 14) bsh[t] = b2[(2 * r2) * 14 + t] + b2[(2 * r2 + 1) * 14 + t];
    __syncthreads();

    unsigned long long wp[30];
#pragma unroll
    for (int i = 0; i < 30; i++) wp[i] = pk2(wsh[f * 30 + i], wsh[(14 + f) * 30 + i]);
    float bias = bsh[f];

    unsigned long long s0 = 0, s1 = 0, s2 = 0, s3 = 0;
    int base = lane * 18;                  // 18 outputs per lane (lanes 0..28)

    if (lane < 29) {
        unsigned long long acc[6];
#pragma unroll
        for (int i = 0; i < 6; i++) acc[i] = 0ull;

#pragma unroll
        for (int cp = 0; cp < 11; cp++) {
            int q0 = 2 * cp;
#pragma unroll
            for (int ci = 0; ci < 6; ci++) {
                float2 a  = *reinterpret_cast<const float2*>(&in[ci][base + q0]);
                float2 c2 = *reinterpret_cast<const float2*>(&in[6 + ci][base + q0]);
                unsigned long long P0 = pk2(a.x, c2.x);
                unsigned long long P1 = pk2(a.y, c2.y);
#pragma unroll
                for (int k = 0; k < 5; k++) {
                    int p0 = q0 - k, p1 = q0 + 1 - k;
                    if (p0 >= 0 && p0 < 18) fma2(acc[(p0 + 12) % 6], P0, wp[ci * 5 + k]);
                    if (p1 >= 0 && p1 < 18) fma2(acc[(p1 + 12) % 6], P1, wp[ci * 5 + k]);
                }
            }
#pragma unroll
            for (int d = 0; d < 2; d++) {
                int pe = 2 * cp - 4 + d;
                if (pe >= 0 && pe < 18) {
                    float lo, hi; upk2(acc[(pe + 12) % 6], lo, hi);
                    float x = lo + hi + bias;
                    int pos = base + pe;
                    if (pos < L2) {
                        unsigned long long e =
                            ((unsigned long long)f2key(x) << 32) |
                            (unsigned int)(1023 - pos);
                        INS4(e)
                    }
                    acc[(pe + 12) % 6] = 0ull;
                }
            }
        }
    }

#pragma unroll
    for (int off = 16; off; off >>= 1) {
        unsigned long long q0 = __shfl_down_sync(0xffffffffu, s0, off);
        unsigned long long q1 = __shfl_down_sync(0xffffffffu, s1, off);
        unsigned long long q2 = __shfl_down_sync(0xffffffffu, s2, off);
        unsigned long long q3 = __shfl_down_sync(0xffffffffu, s3, off);
        MERGE4(s0, s1, s2, s3, q0, q1, q2, q3)
    }
    if (lane == 0) {
        unsigned long long ss[4] = {s0, s1, s2, s3};
        int idx4[4]; float val4[4];
#pragma unroll
        for (int j = 0; j < 4; j++) {
            idx4[j] = 1023 - (int)(unsigned int)(ss[j] & 0xffffffffu);
            val4[j] = key2f((unsigned int)(ss[j] >> 32));
        }
#define CSW(a, bq)                                                              \
    if (idx4[a] > idx4[bq]) {                                                   \
        int ti = idx4[a]; idx4[a] = idx4[bq]; idx4[bq] = ti;                    \
        float tv = val4[a]; val4[a] = val4[bq]; val4[bq] = tv;                   \
    }
        CSW(0, 1) CSW(2, 3) CSW(0, 2) CSW(1, 3) CSW(1, 2)
#undef CSW
        float* o = g_h3 + (size_t)(b * CH2 + (r2 * 14 + f)) * 4;
        o[0] = fast_tanh(val4[0]); o[1] = fast_tanh(val4[1]);
        o[2] = fast_tanh(val4[2]); o[3] = fast_tanh(val4[3]);
    }
}

// ---------------------------------------------------------------------------
// Kernel 4a: split-K GEMM partials. grid (16 cTiles, 56 kz), block 256.
// ---------------------------------------------------------------------------
__global__ __launch_bounds__(256) void k_fcp(const float* __restrict__ wf) {
    __shared__ float sh[32][64];
    __shared__ float sw[64][65];
    int t = threadIdx.x;
    int cb = blockIdx.x, kz = blockIdx.y;
    int bt = t >> 4;   // 0..15 -> b rows 2bt, 2bt+1
    int ct = t & 15;   // 0..15 -> c cols cb*64 + ct + 16j
    float acc[2][4] = {{0.f, 0.f, 0.f, 0.f}, {0.f, 0.f, 0.f, 0.f}};

    int k0 = kz * 64;
#pragma unroll
    for (int i = 0; i < 2; i++) {
        int idx = t + i * 256;
        int row = idx >> 4, cq = (idx & 15) * 4;
        *(float4*)&sh[row][cq] = *(const float4*)&g_h3[row * KF + k0 + cq];
    }
#pragma unroll
    for (int i = 0; i < 4; i++) {
        int idx = t + i * 256;
        int rr = idx >> 4, cq = (idx & 15) * 4;
        int c = cb * 64 + rr;
        float4 v = make_float4(0.f, 0.f, 0.f, 0.f);
        if (c < CC) v = *(const float4*)&wf[(size_t)c * KF + k0 + cq];
        sw[rr][cq] = v.x; sw[rr][cq + 1] = v.y;
        sw[rr][cq + 2] = v.z; sw[rr][cq + 3] = v.w;
    }
    __syncthreads();
#pragma unroll
    for (int kk = 0; kk < 64; kk++) {
        float a0 = sh[2 * bt][kk], a1 = sh[2 * bt + 1][kk];
#pragma unroll
        for (int j = 0; j < 4; j++) {
            float wv = sw[ct + 16 * j][kk];
            acc[0][j] = fmaf(a0, wv, acc[0][j]);
            acc[1][j] = fmaf(a1, wv, acc[1][j]);
        }
    }
#pragma unroll
    for (int i = 0; i < 2; i++)
#pragma unroll
        for (int j = 0; j < 4; j++) {
            int c = cb * 64 + ct + 16 * j;
            if (c < CC)
                g_fcp[(kz * BB + 2 * bt + i) * CC + c] = acc[i][j];
        }
}

// Kernel 4b: deterministic reduce + bias
__global__ __launch_bounds__(256) void k_fcred(const float* __restrict__ bf,
                                               float* __restrict__ out) {
    int i = blockIdx.x * 256 + threadIdx.x;
    if (i >= BB * CC) return;
    int c = i % CC;
    float s = bf[c];
#pragma unroll
    for (int z = 0; z < KSPLIT; z++) s += g_fcp[z * (BB * CC) + i];
    out[i] = s;
}

extern "C" void kernel_launch(void* const* d_in, const int* in_sizes, int n_in,
                              void* d_out, int out_size) {
    (void)in_sizes; (void)n_in; (void)out_size;
    const int*   x   = (const int*)d_in[0];
    const float* emb = (const float*)d_in[1];
    const float* w1  = (const float*)d_in[2];
    const float* b1  = (const float*)d_in[3];
    const float* w2  = (const float*)d_in[4];
    const float* b2  = (const float*)d_in[5];
    const float* wf  = (const float*)d_in[6];
    const float* bf  = (const float*)d_in[7];
    float* out = (float*)d_out;

    k_gather<<<dim3(32, 32), 256>>>(x, emb);
    // conv1 split into 8 grid slices so ncu (-s 5 -c 1) lands on one of them
    for (int i = 0; i < 8; i++)
        k_conv1<<<dim3(16, 32), 192>>>(w1, b1, i * 16);
    k_conv2<<<dim3(64, 32), 448>>>(w2, b2);
    k_fcp<<<dim3(16, KSPLIT), 256>>>(wf);
    k_fcred<<<125, 256>>>(bf, out);
}

// round 16
// speedup vs baseline: 1.2539x; 1.2539x over previous
#include <cuda_runtime.h>

#define BB   32
#define SS   1024
#define DD   256
#define L1   1030      // conv1 output length
#define KSEL 515       // k-max k for layer 1
#define CH1  768       // channels after fold1 (128 groups x 6)
#define L2IN 515
#define L2   519       // conv2 output length
#define CH2  896       // channels after fold2 (64 x 14)
#define CC   1000
#define KF   3584
#define KSPLIT 56      // fc k-splits of 64
#define ABROW 1152     // padded act row: covers uint4 overread to idx 1151, 16B-aligned

// scratch (static device globals; no runtime allocation)
__device__ float g_h0[BB * DD * SS];         // (b, d, s) embedded+transposed
__device__ float g_h1[BB * CH1 * KSEL];      // (b, c1, pos) after kmax+tanh
__device__ float g_h3[BB * CH2 * 4];         // (b, c2, 4) after top4+tanh
__device__ float g_fcp[KSPLIT * BB * CC];    // fc partial sums

__device__ __forceinline__ unsigned int f2key(float v) {
    unsigned int u = __float_as_uint(v);
    return u ^ ((u & 0x80000000u) ? 0xFFFFFFFFu : 0x80000000u);
}
__device__ __forceinline__ float key2f(unsigned int k) {
    unsigned int u = k ^ ((k & 0x80000000u) ? 0x80000000u : 0xFFFFFFFFu);
    return __uint_as_float(u);
}
__device__ __forceinline__ float fast_tanh(float x) {
    float ax = fabsf(x);
    float t = __expf(-2.f * ax);
    float r = __fdividef(1.f - t, 1.f + t);
    return copysignf(r, x);
}

// packed f32x2 helpers (sm_103a FFMA2 path)
__device__ __forceinline__ unsigned long long pk2(float lo, float hi) {
    unsigned long long r;
    asm("mov.b64 %0, {%1,%2};" : "=l"(r) : "f"(lo), "f"(hi));
    return r;
}
__device__ __forceinline__ void upk2(unsigned long long v, float& lo, float& hi) {
    asm("mov.b64 {%0,%1}, %2;" : "=f"(lo), "=f"(hi) : "l"(v));
}
__device__ __forceinline__ void fma2(unsigned long long& d, unsigned long long a,
                                     unsigned long long b) {
    asm("fma.rn.f32x2 %0, %1, %2, %3;" : "=l"(d) : "l"(a), "l"(b), "l"(d));
}

__device__ __forceinline__ int wexscan(int v, int lane) {
    int s = v;
#pragma unroll
    for (int o = 1; o < 32; o <<= 1) {
        int n = __shfl_up_sync(0xffffffffu, s, o);
        if (lane >= o) s += n;
    }
    return s - v;
}
__device__ __forceinline__ unsigned wredAnd(unsigned v) {
#pragma unroll
    for (int o = 16; o; o >>= 1) v &= __shfl_xor_sync(0xffffffffu, v, o);
    return v;
}
__device__ __forceinline__ unsigned wredOr(unsigned v) {
#pragma unroll
    for (int o = 16; o; o >>= 1) v |= __shfl_xor_sync(0xffffffffu, v, o);
    return v;
}
__device__ __forceinline__ int wredAdd(int v) {
#pragma unroll
    for (int o = 16; o; o >>= 1) v += __shfl_xor_sync(0xffffffffu, v, o);
    return v;
}

// ---------------------------------------------------------------------------
// Kernel 1: embedding gather + transpose  (B,S) tokens -> g_h0 (b, d, s)
// ---------------------------------------------------------------------------
__global__ __launch_bounds__(256) void k_gather(const int* __restrict__ x,
                                                const float* __restrict__ emb) {
    __shared__ float tile[32][257];
    __shared__ int toks[32];
    int b = blockIdx.y;
    int sBase = blockIdx.x * 32;
    int t = threadIdx.x;
    if (t < 32) toks[t] = x[b * SS + sBase + t];
    __syncthreads();
    int rowB = t >> 6;         // 0..3
    int col4 = (t & 63) * 4;   // 0..252
#pragma unroll
    for (int i = 0; i < 8; i++) {
        int row = rowB + i * 4;
        const float4 v = *(const float4*)&emb[(size_t)(unsigned)toks[row] * DD + col4];
        tile[row][col4] = v.x; tile[row][col4 + 1] = v.y;
        tile[row][col4 + 2] = v.z; tile[row][col4 + 3] = v.w;
    }
    __syncthreads();
    int sl = t & 31, wg = t >> 5;
#pragma unroll 4
    for (int r = 0; r < 32; r++) {
        int d = wg * 32 + r;
        g_h0[((b * DD + d) << 10) + sBase + sl] = tile[sl][d];
    }
}

// ---------------------------------------------------------------------------
// Kernel 2 v3: conv1 + fold + order-preserving k-max(515/1030) + tanh.
//   One WARP per selection row. No register key cache (lower regs -> more
//   blocks/SM). Search: AND/OR bit-skip radix with uint4-vectorized count &
//   compaction. Epilogue: recompute conv (bit-identical fma2 chain), then
//   stable compaction.
// ---------------------------------------------------------------------------
__global__ __launch_bounds__(192) void k_conv1(const float* __restrict__ w1,
                                               const float* __restrict__ b1) {
    __shared__ unsigned long long e01[1064];       // packed {ch0, ch1}
    __shared__ unsigned int act[6][ABROW];         // per-warp buffer

    int r = blockIdx.x, b = blockIdx.y;
    int t = threadIdx.x;
    int f = t >> 5, lane = t & 31;
    unsigned lt = (1u << lane) - 1u;

    const float* s0 = g_h0 + ((b * DD + 2 * r) << 10);
    for (int m = t; m < 1064; m += 192) {
        float v0 = 0.f, v1 = 0.f;
        if (m >= 6 && m < 6 + SS) { v0 = s0[m - 6]; v1 = s0[SS + m - 6]; }
        e01[m] = pk2(v0, v1);
    }
    __syncthreads();

    int o0 = (2 * r) * 6 + f, o1 = (2 * r + 1) * 6 + f;
    float bias = b1[o0] + b1[o1];
    unsigned long long W[7];
#pragma unroll
    for (int k = 0; k < 7; k++) W[k] = pk2(w1[o0 * 7 + k], w1[o1 * 7 + k]);

    int base = lane * 33;
    unsigned int* ab = act[f];

    // ---- pass 1: conv -> ab, AND/OR stats (no register key cache) ----
    {
        unsigned long long P[7];
#pragma unroll
        for (int k = 0; k < 7; k++) P[k] = e01[base + k];
        unsigned aAll = 0xFFFFFFFFu, oAll = 0u;
#pragma unroll
        for (int j = 0; j < 33; j++) {
            unsigned long long acc = pk2(bias, 0.f);
#pragma unroll
            for (int k = 0; k < 7; k++) fma2(acc, P[k], W[k]);
            float lo, hi; upk2(acc, lo, hi);
            int valid = (j < 7) || (lane < 31);
            if (valid) {
                unsigned kk = f2key(lo + hi);
                ab[base + j] = kk;
                aAll &= kk; oAll |= kk;
            }
#pragma unroll
            for (int k = 0; k < 6; k++) P[k] = P[k + 1];
            P[6] = e01[base + j + 7];
        }
        __syncwarp();
        unsigned andA = wredAnd(aAll), orA = wredOr(oAll);

        // ---- bit-skipping radix threshold search (uint4 vectorized) ----
        int g = 0, A = L1;
#pragma unroll 1
        for (int it = 0; it < 32; it++) {
            unsigned diff = andA ^ orA;
            if (diff == 0u) break;
            int bpos = 31 - __clz(diff);
            int n128 = (A + 127) >> 7;
            // count pass (padded row: overread up to idx 1151 is in-bounds)
            int cnt = 0;
#pragma unroll 1
            for (int ch = 0; ch < n128; ch++) {
                int ix = (ch << 7) + (lane << 2);
                uint4 v = *(const uint4*)&ab[ix];
                cnt += (ix     < A) & (int)((v.x >> bpos) & 1u);
                cnt += (ix + 1 < A) & (int)((v.y >> bpos) & 1u);
                cnt += (ix + 2 < A) & (int)((v.z >> bpos) & 1u);
                cnt += (ix + 3 < A) & (int)((v.w >> bpos) & 1u);
            }
            int c = wredAdd(cnt);
            int keepHigh = (g + c >= KSEL);
            // compact kept side to front (in-place safe: writes trail reads)
            unsigned na = 0xFFFFFFFFu, no = 0u;
            int nw = 0;
#pragma unroll 1
            for (int ch = 0; ch < n128; ch++) {
                int ix = (ch << 7) + (lane << 2);
                uint4 v = *(const uint4*)&ab[ix];
                unsigned vv[4] = {v.x, v.y, v.z, v.w};
#pragma unroll
                for (int q = 0; q < 4; q++) {
                    int i2 = ix + q;
                    int keep = (i2 < A) &&
                               ((int)((vv[q] >> bpos) & 1u) == keepHigh);
                    unsigned bal = __ballot_sync(0xffffffffu, keep);
                    if (keep) {
                        ab[nw + __popc(bal & lt)] = vv[q];
                        na &= vv[q]; no |= vv[q];
                    }
                    nw += __popc(bal);
                }
            }
            if (!keepHigh) g += c;
            A = nw;
            andA = wredAnd(na);
            orA = wredOr(no);
            __syncwarp();
        }
        unsigned T = andA;
        int limit = KSEL - g;

        // ---- epilogue E1: recompute conv (bit-identical) -> ab + counts ----
#pragma unroll
        for (int k = 0; k < 7; k++) P[k] = e01[base + k];
        int cntG = 0, cntE = 0;
#pragma unroll
        for (int j = 0; j < 33; j++) {
            unsigned long long acc = pk2(bias, 0.f);
#pragma unroll
            for (int k = 0; k < 7; k++) fma2(acc, P[k], W[k]);
            float lo, hi; upk2(acc, lo, hi);
            int valid = (j < 7) || (lane < 31);
            if (valid) {
                unsigned kk = f2key(lo + hi);
                ab[base + j] = kk;
                cntG += (kk > T);
                cntE += (kk == T);
            }
#pragma unroll
            for (int k = 0; k < 6; k++) P[k] = P[k + 1];
            P[6] = e01[base + j + 7];
        }
        int eqBefore = wexscan(cntE, lane);
        int eqTake = limit - eqBefore;
        if (eqTake < 0) eqTake = 0;
        if (eqTake > cntE) eqTake = cntE;
        int keepCnt = cntG + eqTake;
        int wrBase = wexscan(keepCnt, lane);

        // ---- E2: stable compaction + tanh (reads own lane's writes) ----
        float* orow = g_h1 + (size_t)(b * CH1 + r * 6 + f) * KSEL;
        int eq = eqBefore, wr = wrBase;
#pragma unroll
        for (int j = 0; j < 33; j++) {
            int valid = (j < 7) || (lane < 31);
            if (valid) {
                unsigned kk = ab[base + j];
                int isG = kk > T;
                int isE = kk == T;
                int kept = isG || (isE && (eq < limit));
                eq += isE;
                if (kept) { orow[wr] = fast_tanh(key2f(kk)); wr++; }
            }
        }
    }
}

// top-4 merge of two descending sorted-4 u64 lists
#define MERGE4(a0, a1, a2, a3, q0, q1, q2, q3)                                  \
    {                                                                           \
        unsigned long long m0 = (a0) > (q3) ? (a0) : (q3);                      \
        unsigned long long m1 = (a1) > (q2) ? (a1) : (q2);                      \
        unsigned long long m2 = (a2) > (q1) ? (a2) : (q1);                      \
        unsigned long long m3 = (a3) > (q0) ? (a3) : (q0);                      \
        unsigned long long d0 = m0 > m2 ? m0 : m2, d2 = m0 > m2 ? m2 : m0;      \
        unsigned long long d1 = m1 > m3 ? m1 : m3, d3 = m1 > m3 ? m3 : m1;      \
        a0 = d0 > d1 ? d0 : d1; a1 = d0 > d1 ? d1 : d0;                         \
        a2 = d2 > d3 ? d2 : d3; a3 = d2 > d3 ? d3 : d2;                         \
    }
#define INS4(e)                                                                 \
    {                                                                           \
        if ((e) > s0)      { s3 = s2; s2 = s1; s1 = s0; s0 = (e); }             \
        else if ((e) > s1) { s3 = s2; s2 = s1; s1 = (e); }                      \
        else if ((e) > s2) { s3 = s2; s2 = (e); }                               \
        else if ((e) > s3) { s3 = (e); }                                        \
    }

// ---------------------------------------------------------------------------
// Kernel 3 v2: conv2(K=5, grouped 6->14, packed FMA2) + top-4 + tanh.
//   One WARP per filter; weights streamed from smem per (chunk, ci).
//   Inputs via conflict-free ulonglong2. Launched in 4 grid slices (roff).
// ---------------------------------------------------------------------------
__global__ __launch_bounds__(448) void k_conv2(const float* __restrict__ w2,
                                               const float* __restrict__ b2,
                                               int roff) {
    __shared__ unsigned long long inP[6][552];   // packed {groupA, groupB}
    __shared__ unsigned long long wpk[420];      // 14 filters x 30 packed
    __shared__ float bsh[14];

    int r2 = roff + blockIdx.x, b = blockIdx.y;
    int t = threadIdx.x, lane = t & 31, f = t >> 5;

    const float* src = g_h1 + (size_t)(b * CH1 + r2 * 12) * KSEL;
    for (int idx = t; idx < 6 * 552; idx += 448) {
        int ci = idx / 552, m = idx - ci * 552;
        float v0 = 0.f, v1 = 0.f;
        if (m >= 4 && m < 4 + L2IN) {
            v0 = src[ci * KSEL + m - 4];
            v1 = src[(ci + 6) * KSEL + m - 4];
        }
        inP[ci][m] = pk2(v0, v1);
    }
    for (int idx = t; idx < 420; idx += 448) {
        int ff = idx / 30, rem = idx - ff * 30;
        wpk[idx] = pk2(w2[((2 * r2) * 14 + ff) * 30 + rem],
                       w2[((2 * r2 + 1) * 14 + ff) * 30 + rem]);
    }
    if (t < 14) bsh[t] = b2[(2 * r2) * 14 + t] + b2[(2 * r2 + 1) * 14 + t];
    __syncthreads();

    float bias = bsh[f];
    unsigned long long s0 = 0, s1 = 0, s2 = 0, s3 = 0;
    int base = lane * 18;                 // lanes 0..28 own 18 positions each

    if (lane < 29) {
#pragma unroll
        for (int c = 0; c < 3; c++) {
            int st = base + 6 * c;        // even => 16B-aligned u64 pairs
            unsigned long long acc[6];
#pragma unroll
            for (int i = 0; i < 6; i++) acc[i] = 0ull;
#pragma unroll
            for (int ci = 0; ci < 6; ci++) {
                const unsigned long long* wr = &wpk[f * 30 + ci * 5];
                unsigned long long w0 = wr[0], w1_ = wr[1], w2_ = wr[2],
                                   w3 = wr[3], w4 = wr[4];
                const unsigned long long* ip = &inP[ci][st];
                ulonglong2 a  = *(const ulonglong2*)&ip[0];
                ulonglong2 bq = *(const ulonglong2*)&ip[2];
                ulonglong2 cc = *(const ulonglong2*)&ip[4];
                ulonglong2 dd = *(const ulonglong2*)&ip[6];
                ulonglong2 ee = *(const ulonglong2*)&ip[8];
                unsigned long long v0 = a.x, v1 = a.y, v2 = bq.x, v3 = bq.y,
                                   v4 = cc.x, v5 = cc.y, v6 = dd.x, v7 = dd.y,
                                   v8 = ee.x, v9 = ee.y;
                fma2(acc[0], v0, w0); fma2(acc[0], v1, w1_); fma2(acc[0], v2, w2_);
                fma2(acc[0], v3, w3); fma2(acc[0], v4, w4);
                fma2(acc[1], v1, w0); fma2(acc[1], v2, w1_); fma2(acc[1], v3, w2_);
                fma2(acc[1], v4, w3); fma2(acc[1], v5, w4);
                fma2(acc[2], v2, w0); fma2(acc[2], v3, w1_); fma2(acc[2], v4, w2_);
                fma2(acc[2], v5, w3); fma2(acc[2], v6, w4);
                fma2(acc[3], v3, w0); fma2(acc[3], v4, w1_); fma2(acc[3], v5, w2_);
                fma2(acc[3], v6, w3); fma2(acc[3], v7, w4);
                fma2(acc[4], v4, w0); fma2(acc[4], v5, w1_); fma2(acc[4], v6, w2_);
                fma2(acc[4], v7, w3); fma2(acc[4], v8, w4);
                fma2(acc[5], v5, w0); fma2(acc[5], v6, w1_); fma2(acc[5], v7, w2_);
                fma2(acc[5], v8, w3); fma2(acc[5], v9, w4);
            }
#pragma unroll
            for (int d = 0; d < 6; d++) {
                int pos = st + d;
                if (pos < L2) {
                    float lo, hi; upk2(acc[d], lo, hi);
                    float x = lo + hi + bias;
                    unsigned long long e =
                        ((unsigned long long)f2key(x) << 32) |
                        (unsigned int)(1023 - pos);
                    INS4(e)
                }
            }
        }
    }

#pragma unroll
    for (int off = 16; off; off >>= 1) {
        unsigned long long q0 = __shfl_down_sync(0xffffffffu, s0, off);
        unsigned long long q1 = __shfl_down_sync(0xffffffffu, s1, off);
        unsigned long long q2 = __shfl_down_sync(0xffffffffu, s2, off);
        unsigned long long q3 = __shfl_down_sync(0xffffffffu, s3, off);
        MERGE4(s0, s1, s2, s3, q0, q1, q2, q3)
    }
    if (lane == 0) {
        unsigned long long ss[4] = {s0, s1, s2, s3};
        int idx4[4]; float val4[4];
#pragma unroll
        for (int j = 0; j < 4; j++) {
            idx4[j] = 1023 - (int)(unsigned int)(ss[j] & 0xffffffffu);
            val4[j] = key2f((unsigned int)(ss[j] >> 32));
        }
#define CSW(a, bq)                                                              \
    if (idx4[a] > idx4[bq]) {                                                   \
        int ti = idx4[a]; idx4[a] = idx4[bq]; idx4[bq] = ti;                    \
        float tv = val4[a]; val4[a] = val4[bq]; val4[bq] = tv;                   \
    }
        CSW(0, 1) CSW(2, 3) CSW(0, 2) CSW(1, 3) CSW(1, 2)
#undef CSW
        float* o = g_h3 + (size_t)(b * CH2 + (r2 * 14 + f)) * 4;
        o[0] = fast_tanh(val4[0]); o[1] = fast_tanh(val4[1]);
        o[2] = fast_tanh(val4[2]); o[3] = fast_tanh(val4[3]);
    }
}

// ---------------------------------------------------------------------------
// Kernel 4a: split-K GEMM partials. grid (16 cTiles, 56 kz), block 256.
// ---------------------------------------------------------------------------
__global__ __launch_bounds__(256) void k_fcp(const float* __restrict__ wf) {
    __shared__ float sh[32][64];
    __shared__ float sw[64][65];
    int t = threadIdx.x;
    int cb = blockIdx.x, kz = blockIdx.y;
    int bt = t >> 4;   // 0..15 -> b rows 2bt, 2bt+1
    int ct = t & 15;   // 0..15 -> c cols cb*64 + ct + 16j
    float acc[2][4] = {{0.f, 0.f, 0.f, 0.f}, {0.f, 0.f, 0.f, 0.f}};

    int k0 = kz * 64;
#pragma unroll
    for (int i = 0; i < 2; i++) {
        int idx = t + i * 256;
        int row = idx >> 4, cq = (idx & 15) * 4;
        *(float4*)&sh[row][cq] = *(const float4*)&g_h3[row * KF + k0 + cq];
    }
#pragma unroll
    for (int i = 0; i < 4; i++) {
        int idx = t + i * 256;
        int rr = idx >> 4, cq = (idx & 15) * 4;
        int c = cb * 64 + rr;
        float4 v = make_float4(0.f, 0.f, 0.f, 0.f);
        if (c < CC) v = *(const float4*)&wf[(size_t)c * KF + k0 + cq];
        sw[rr][cq] = v.x; sw[rr][cq + 1] = v.y;
        sw[rr][cq + 2] = v.z; sw[rr][cq + 3] = v.w;
    }
    __syncthreads();
#pragma unroll
    for (int kk = 0; kk < 64; kk++) {
        float a0 = sh[2 * bt][kk], a1 = sh[2 * bt + 1][kk];
#pragma unroll
        for (int j = 0; j < 4; j++) {
            float wv = sw[ct + 16 * j][kk];
            acc[0][j] = fmaf(a0, wv, acc[0][j]);
            acc[1][j] = fmaf(a1, wv, acc[1][j]);
        }
    }
#pragma unroll
    for (int i = 0; i < 2; i++)
#pragma unroll
        for (int j = 0; j < 4; j++) {
            int c = cb * 64 + ct + 16 * j;
            if (c < CC)
                g_fcp[(kz * BB + 2 * bt + i) * CC + c] = acc[i][j];
        }
}

// Kernel 4b: deterministic reduce + bias
__global__ __launch_bounds__(256) void k_fcred(const float* __restrict__ bf,
                                               float* __restrict__ out) {
    int i = blockIdx.x * 256 + threadIdx.x;
    if (i >= BB * CC) return;
    int c = i % CC;
    float s = bf[c];
#pragma unroll
    for (int z = 0; z < KSPLIT; z++) s += g_fcp[z * (BB * CC) + i];
    out[i] = s;
}

extern "C" void kernel_launch(void* const* d_in, const int* in_sizes, int n_in,
                              void* d_out, int out_size) {
    (void)in_sizes; (void)n_in; (void)out_size;
    const int*   x   = (const int*)d_in[0];
    const float* emb = (const float*)d_in[1];
    const float* w1  = (const float*)d_in[2];
    const float* b1  = (const float*)d_in[3];
    const float* w2  = (const float*)d_in[4];
    const float* b2  = (const float*)d_in[5];
    const float* wf  = (const float*)d_in[6];
    const float* bf  = (const float*)d_in[7];
    float* out = (float*)d_out;

    k_gather<<<dim3(32, 32), 256>>>(x, emb);
    k_conv1<<<dim3(128, 32), 192>>>(w1, b1);
    // conv2 in 4 slices so ncu (-s 5 -c 1) lands on one of them
    for (int i = 0; i < 4; i++)
        k_conv2<<<dim3(16, 32), 448>>>(w2, b2, i * 16);
    k_fcp<<<dim3(16, KSPLIT), 256>>>(wf);
    k_fcred<<<125, 256>>>(bf, out);
}

// round 17
// speedup vs baseline: 1.4905x; 1.1887x over previous
#include <cuda_runtime.h>

#define BB   32
#define SS   1024
#define DD   256
#define L1   1030      // conv1 output length
#define KSEL 515       // k-max k for layer 1
#define CH1  768       // channels after fold1 (128 groups x 6)
#define L2IN 515
#define L2   519       // conv2 output length
#define CH2  896       // channels after fold2 (64 x 14)
#define CC   1000
#define KF   3584
#define KSPLIT 56      // fc k-splits of 64
#define ABROW 1152     // padded act row: covers uint4 overread to idx 1151, 16B-aligned

// scratch (static device globals; no runtime allocation)
__device__ float g_h0[BB * DD * SS];         // (b, d, s) embedded+transposed
__device__ float g_h1[BB * CH1 * KSEL];      // (b, c1, pos) after kmax+tanh
__device__ float g_h3[BB * CH2 * 4];         // (b, c2, 4) after top4+tanh
__device__ float g_fcp[KSPLIT * BB * CC];    // fc partial sums

__device__ __forceinline__ unsigned int f2key(float v) {
    unsigned int u = __float_as_uint(v);
    return u ^ ((u & 0x80000000u) ? 0xFFFFFFFFu : 0x80000000u);
}
__device__ __forceinline__ float key2f(unsigned int k) {
    unsigned int u = k ^ ((k & 0x80000000u) ? 0x80000000u : 0xFFFFFFFFu);
    return __uint_as_float(u);
}
__device__ __forceinline__ float fast_tanh(float x) {
    float ax = fabsf(x);
    float t = __expf(-2.f * ax);
    float r = __fdividef(1.f - t, 1.f + t);
    return copysignf(r, x);
}

// packed f32x2 helpers (sm_103a FFMA2 path)
__device__ __forceinline__ unsigned long long pk2(float lo, float hi) {
    unsigned long long r;
    asm("mov.b64 %0, {%1,%2};" : "=l"(r) : "f"(lo), "f"(hi));
    return r;
}
__device__ __forceinline__ void upk2(unsigned long long v, float& lo, float& hi) {
    asm("mov.b64 {%0,%1}, %2;" : "=f"(lo), "=f"(hi) : "l"(v));
}
__device__ __forceinline__ void fma2(unsigned long long& d, unsigned long long a,
                                     unsigned long long b) {
    asm("fma.rn.f32x2 %0, %1, %2, %3;" : "=l"(d) : "l"(a), "l"(b), "l"(d));
}

__device__ __forceinline__ int wexscan(int v, int lane) {
    int s = v;
#pragma unroll
    for (int o = 1; o < 32; o <<= 1) {
        int n = __shfl_up_sync(0xffffffffu, s, o);
        if (lane >= o) s += n;
    }
    return s - v;
}
__device__ __forceinline__ unsigned wredAnd(unsigned v) {
#pragma unroll
    for (int o = 16; o; o >>= 1) v &= __shfl_xor_sync(0xffffffffu, v, o);
    return v;
}
__device__ __forceinline__ unsigned wredOr(unsigned v) {
#pragma unroll
    for (int o = 16; o; o >>= 1) v |= __shfl_xor_sync(0xffffffffu, v, o);
    return v;
}
__device__ __forceinline__ int wredAdd(int v) {
#pragma unroll
    for (int o = 16; o; o >>= 1) v += __shfl_xor_sync(0xffffffffu, v, o);
    return v;
}

// ---------------------------------------------------------------------------
// Kernel 1: embedding gather + transpose  (B,S) tokens -> g_h0 (b, d, s)
// ---------------------------------------------------------------------------
__global__ __launch_bounds__(256) void k_gather(const int* __restrict__ x,
                                                const float* __restrict__ emb) {
    __shared__ float tile[32][257];
    __shared__ int toks[32];
    int b = blockIdx.y;
    int sBase = blockIdx.x * 32;
    int t = threadIdx.x;
    if (t < 32) toks[t] = x[b * SS + sBase + t];
    __syncthreads();
    int rowB = t >> 6;         // 0..3
    int col4 = (t & 63) * 4;   // 0..252
#pragma unroll
    for (int i = 0; i < 8; i++) {
        int row = rowB + i * 4;
        const float4 v = *(const float4*)&emb[(size_t)(unsigned)toks[row] * DD + col4];
        tile[row][col4] = v.x; tile[row][col4 + 1] = v.y;
        tile[row][col4 + 2] = v.z; tile[row][col4 + 3] = v.w;
    }
    __syncthreads();
    int sl = t & 31, wg = t >> 5;
#pragma unroll 4
    for (int r = 0; r < 32; r++) {
        int d = wg * 32 + r;
        g_h0[((b * DD + d) << 10) + sBase + sl] = tile[sl][d];
    }
}

// ---------------------------------------------------------------------------
// Kernel 2 v3: conv1 + fold + order-preserving k-max(515/1030) + tanh.
//   One WARP per selection row. AND/OR bit-skip radix search with
//   uint4-vectorized count & compaction; bit-identical conv recompute.
// ---------------------------------------------------------------------------
__global__ __launch_bounds__(192) void k_conv1(const float* __restrict__ w1,
                                               const float* __restrict__ b1) {
    __shared__ unsigned long long e01[1064];       // packed {ch0, ch1}
    __shared__ unsigned int act[6][ABROW];         // per-warp buffer

    int r = blockIdx.x, b = blockIdx.y;
    int t = threadIdx.x;
    int f = t >> 5, lane = t & 31;
    unsigned lt = (1u << lane) - 1u;

    const float* s0 = g_h0 + ((b * DD + 2 * r) << 10);
    for (int m = t; m < 1064; m += 192) {
        float v0 = 0.f, v1 = 0.f;
        if (m >= 6 && m < 6 + SS) { v0 = s0[m - 6]; v1 = s0[SS + m - 6]; }
        e01[m] = pk2(v0, v1);
    }
    __syncthreads();

    int o0 = (2 * r) * 6 + f, o1 = (2 * r + 1) * 6 + f;
    float bias = b1[o0] + b1[o1];
    unsigned long long W[7];
#pragma unroll
    for (int k = 0; k < 7; k++) W[k] = pk2(w1[o0 * 7 + k], w1[o1 * 7 + k]);

    int base = lane * 33;
    unsigned int* ab = act[f];

    {
        unsigned long long P[7];
#pragma unroll
        for (int k = 0; k < 7; k++) P[k] = e01[base + k];
        unsigned aAll = 0xFFFFFFFFu, oAll = 0u;
#pragma unroll
        for (int j = 0; j < 33; j++) {
            unsigned long long acc = pk2(bias, 0.f);
#pragma unroll
            for (int k = 0; k < 7; k++) fma2(acc, P[k], W[k]);
            float lo, hi; upk2(acc, lo, hi);
            int valid = (j < 7) || (lane < 31);
            if (valid) {
                unsigned kk = f2key(lo + hi);
                ab[base + j] = kk;
                aAll &= kk; oAll |= kk;
            }
#pragma unroll
            for (int k = 0; k < 6; k++) P[k] = P[k + 1];
            P[6] = e01[base + j + 7];
        }
        __syncwarp();
        unsigned andA = wredAnd(aAll), orA = wredOr(oAll);

        // ---- bit-skipping radix threshold search (uint4 vectorized) ----
        int g = 0, A = L1;
#pragma unroll 1
        for (int it = 0; it < 32; it++) {
            unsigned diff = andA ^ orA;
            if (diff == 0u) break;
            int bpos = 31 - __clz(diff);
            int n128 = (A + 127) >> 7;
            int cnt = 0;
#pragma unroll 1
            for (int ch = 0; ch < n128; ch++) {
                int ix = (ch << 7) + (lane << 2);
                uint4 v = *(const uint4*)&ab[ix];
                cnt += (ix     < A) & (int)((v.x >> bpos) & 1u);
                cnt += (ix + 1 < A) & (int)((v.y >> bpos) & 1u);
                cnt += (ix + 2 < A) & (int)((v.z >> bpos) & 1u);
                cnt += (ix + 3 < A) & (int)((v.w >> bpos) & 1u);
            }
            int c = wredAdd(cnt);
            int keepHigh = (g + c >= KSEL);
            unsigned na = 0xFFFFFFFFu, no = 0u;
            int nw = 0;
#pragma unroll 1
            for (int ch = 0; ch < n128; ch++) {
                int ix = (ch << 7) + (lane << 2);
                uint4 v = *(const uint4*)&ab[ix];
                unsigned vv[4] = {v.x, v.y, v.z, v.w};
#pragma unroll
                for (int q = 0; q < 4; q++) {
                    int i2 = ix + q;
                    int keep = (i2 < A) &&
                               ((int)((vv[q] >> bpos) & 1u) == keepHigh);
                    unsigned bal = __ballot_sync(0xffffffffu, keep);
                    if (keep) {
                        ab[nw + __popc(bal & lt)] = vv[q];
                        na &= vv[q]; no |= vv[q];
                    }
                    nw += __popc(bal);
                }
            }
            if (!keepHigh) g += c;
            A = nw;
            andA = wredAnd(na);
            orA = wredOr(no);
            __syncwarp();
        }
        unsigned T = andA;
        int limit = KSEL - g;

        // ---- epilogue: recompute conv (bit-identical) -> ab + counts ----
#pragma unroll
        for (int k = 0; k < 7; k++) P[k] = e01[base + k];
        int cntG = 0, cntE = 0;
#pragma unroll
        for (int j = 0; j < 33; j++) {
            unsigned long long acc = pk2(bias, 0.f);
#pragma unroll
            for (int k = 0; k < 7; k++) fma2(acc, P[k], W[k]);
            float lo, hi; upk2(acc, lo, hi);
            int valid = (j < 7) || (lane < 31);
            if (valid) {
                unsigned kk = f2key(lo + hi);
                ab[base + j] = kk;
                cntG += (kk > T);
                cntE += (kk == T);
            }
#pragma unroll
            for (int k = 0; k < 6; k++) P[k] = P[k + 1];
            P[6] = e01[base + j + 7];
        }
        int eqBefore = wexscan(cntE, lane);
        int eqTake = limit - eqBefore;
        if (eqTake < 0) eqTake = 0;
        if (eqTake > cntE) eqTake = cntE;
        int keepCnt = cntG + eqTake;
        int wrBase = wexscan(keepCnt, lane);

        float* orow = g_h1 + (size_t)(b * CH1 + r * 6 + f) * KSEL;
        int eq = eqBefore, wr = wrBase;
#pragma unroll
        for (int j = 0; j < 33; j++) {
            int valid = (j < 7) || (lane < 31);
            if (valid) {
                unsigned kk = ab[base + j];
                int isG = kk > T;
                int isE = kk == T;
                int kept = isG || (isE && (eq < limit));
                eq += isE;
                if (kept) { orow[wr] = fast_tanh(key2f(kk)); wr++; }
            }
        }
    }
}

// top-4 merge of two descending sorted-4 u64 lists
#define MERGE4(a0, a1, a2, a3, q0, q1, q2, q3)                                  \
    {                                                                           \
        unsigned long long m0 = (a0) > (q3) ? (a0) : (q3);                      \
        unsigned long long m1 = (a1) > (q2) ? (a1) : (q2);                      \
        unsigned long long m2 = (a2) > (q1) ? (a2) : (q1);                      \
        unsigned long long m3 = (a3) > (q0) ? (a3) : (q0);                      \
        unsigned long long d0 = m0 > m2 ? m0 : m2, d2 = m0 > m2 ? m2 : m0;      \
        unsigned long long d1 = m1 > m3 ? m1 : m3, d3 = m1 > m3 ? m3 : m1;      \
        a0 = d0 > d1 ? d0 : d1; a1 = d0 > d1 ? d1 : d0;                         \
        a2 = d2 > d3 ? d2 : d3; a3 = d2 > d3 ? d3 : d2;                         \
    }
#define INS4(e)                                                                 \
    {                                                                           \
        if ((e) > s0)      { s3 = s2; s2 = s1; s1 = s0; s0 = (e); }             \
        else if ((e) > s1) { s3 = s2; s2 = s1; s1 = (e); }                      \
        else if ((e) > s2) { s3 = s2; s2 = (e); }                               \
        else if ((e) > s3) { s3 = (e); }                                        \
    }

// ---------------------------------------------------------------------------
// Kernel 3 v3: conv2(K=5, grouped 6->14, packed FMA2) + top-4 + tanh.
//   One WARP per filter. ci loop kept at unroll 1 so ptxas does NOT batch
//   all 6 iterations' input loads (round-16 profile: regs=128 -> 1 blk/SM).
//   Target ~64-72 regs -> 2 blocks/SM (28 warps). Unsliced.
// ---------------------------------------------------------------------------
__global__ __launch_bounds__(448) void k_conv2(const float* __restrict__ w2,
                                               const float* __restrict__ b2) {
    __shared__ unsigned long long inP[6][552];   // packed {groupA, groupB}
    __shared__ unsigned long long wpk[420];      // 14 filters x 30 packed
    __shared__ float bsh[14];

    int r2 = blockIdx.x, b = blockIdx.y;
    int t = threadIdx.x, lane = t & 31, f = t >> 5;

    const float* src = g_h1 + (size_t)(b * CH1 + r2 * 12) * KSEL;
    for (int idx = t; idx < 6 * 552; idx += 448) {
        int ci = idx / 552, m = idx - ci * 552;
        float v0 = 0.f, v1 = 0.f;
        if (m >= 4 && m < 4 + L2IN) {
            v0 = src[ci * KSEL + m - 4];
            v1 = src[(ci + 6) * KSEL + m - 4];
        }
        inP[ci][m] = pk2(v0, v1);
    }
    for (int idx = t; idx < 420; idx += 448) {
        int ff = idx / 30, rem = idx - ff * 30;
        wpk[idx] = pk2(w2[((2 * r2) * 14 + ff) * 30 + rem],
                       w2[((2 * r2 + 1) * 14 + ff) * 30 + rem]);
    }
    if (t < 14) bsh[t] = b2[(2 * r2) * 14 + t] + b2[(2 * r2 + 1) * 14 + t];
    __syncthreads();

    float bias = bsh[f];
    unsigned long long s0 = 0, s1 = 0, s2 = 0, s3 = 0;
    int base = lane * 18;                 // lanes 0..28 own 18 positions each

    if (lane < 29) {
#pragma unroll 1
        for (int c = 0; c < 3; c++) {
            int st = base + 6 * c;        // even => 16B-aligned u64 pairs
            unsigned long long acc[6];
#pragma unroll
            for (int i = 0; i < 6; i++) acc[i] = 0ull;
#pragma unroll 1
            for (int ci = 0; ci < 6; ci++) {
                const unsigned long long* wr = &wpk[f * 30 + ci * 5];
                unsigned long long w0 = wr[0], w1_ = wr[1], w2_ = wr[2],
                                   w3 = wr[3], w4 = wr[4];
                const unsigned long long* ip = &inP[ci][st];
                ulonglong2 a  = *(const ulonglong2*)&ip[0];
                ulonglong2 bq = *(const ulonglong2*)&ip[2];
                ulonglong2 cc = *(const ulonglong2*)&ip[4];
                ulonglong2 dd = *(const ulonglong2*)&ip[6];
                ulonglong2 ee = *(const ulonglong2*)&ip[8];
                unsigned long long v0 = a.x, v1 = a.y, v2 = bq.x, v3 = bq.y,
                                   v4 = cc.x, v5 = cc.y, v6 = dd.x, v7 = dd.y,
                                   v8 = ee.x, v9 = ee.y;
                fma2(acc[0], v0, w0); fma2(acc[0], v1, w1_); fma2(acc[0], v2, w2_);
                fma2(acc[0], v3, w3); fma2(acc[0], v4, w4);
                fma2(acc[1], v1, w0); fma2(acc[1], v2, w1_); fma2(acc[1], v3, w2_);
                fma2(acc[1], v4, w3); fma2(acc[1], v5, w4);
                fma2(acc[2], v2, w0); fma2(acc[2], v3, w1_); fma2(acc[2], v4, w2_);
                fma2(acc[2], v5, w3); fma2(acc[2], v6, w4);
                fma2(acc[3], v3, w0); fma2(acc[3], v4, w1_); fma2(acc[3], v5, w2_);
                fma2(acc[3], v6, w3); fma2(acc[3], v7, w4);
                fma2(acc[4], v4, w0); fma2(acc[4], v5, w1_); fma2(acc[4], v6, w2_);
                fma2(acc[4], v7, w3); fma2(acc[4], v8, w4);
                fma2(acc[5], v5, w0); fma2(acc[5], v6, w1_); fma2(acc[5], v7, w2_);
                fma2(acc[5], v8, w3); fma2(acc[5], v9, w4);
            }
#pragma unroll
            for (int d = 0; d < 6; d++) {
                int pos = st + d;
                if (pos < L2) {
                    float lo, hi; upk2(acc[d], lo, hi);
                    float x = lo + hi + bias;
                    unsigned long long e =
                        ((unsigned long long)f2key(x) << 32) |
                        (unsigned int)(1023 - pos);
                    INS4(e)
                }
            }
        }
    }

#pragma unroll
    for (int off = 16; off; off >>= 1) {
        unsigned long long q0 = __shfl_down_sync(0xffffffffu, s0, off);
        unsigned long long q1 = __shfl_down_sync(0xffffffffu, s1, off);
        unsigned long long q2 = __shfl_down_sync(0xffffffffu, s2, off);
        unsigned long long q3 = __shfl_down_sync(0xffffffffu, s3, off);
        MERGE4(s0, s1, s2, s3, q0, q1, q2, q3)
    }
    if (lane == 0) {
        unsigned long long ss[4] = {s0, s1, s2, s3};
        int idx4[4]; float val4[4];
#pragma unroll
        for (int j = 0; j < 4; j++) {
            idx4[j] = 1023 - (int)(unsigned int)(ss[j] & 0xffffffffu);
            val4[j] = key2f((unsigned int)(ss[j] >> 32));
        }
#define CSW(a, bq)                                                              \
    if (idx4[a] > idx4[bq]) {                                                   \
        int ti = idx4[a]; idx4[a] = idx4[bq]; idx4[bq] = ti;                    \
        float tv = val4[a]; val4[a] = val4[bq]; val4[bq] = tv;                   \
    }
        CSW(0, 1) CSW(2, 3) CSW(0, 2) CSW(1, 3) CSW(1, 2)
#undef CSW
        float* o = g_h3 + (size_t)(b * CH2 + (r2 * 14 + f)) * 4;
        o[0] = fast_tanh(val4[0]); o[1] = fast_tanh(val4[1]);
        o[2] = fast_tanh(val4[2]); o[3] = fast_tanh(val4[3]);
    }
}

// ---------------------------------------------------------------------------
// Kernel 4a: split-K GEMM partials. grid (16 cTiles, 56 kz), block 256.
// ---------------------------------------------------------------------------
__global__ __launch_bounds__(256) void k_fcp(const float* __restrict__ wf) {
    __shared__ float sh[32][64];
    __shared__ float sw[64][65];
    int t = threadIdx.x;
    int cb = blockIdx.x, kz = blockIdx.y;
    int bt = t >> 4;   // 0..15 -> b rows 2bt, 2bt+1
    int ct = t & 15;   // 0..15 -> c cols cb*64 + ct + 16j
    float acc[2][4] = {{0.f, 0.f, 0.f, 0.f}, {0.f, 0.f, 0.f, 0.f}};

    int k0 = kz * 64;
#pragma unroll
    for (int i = 0; i < 2; i++) {
        int idx = t + i * 256;
        int row = idx >> 4, cq = (idx & 15) * 4;
        *(float4*)&sh[row][cq] = *(const float4*)&g_h3[row * KF + k0 + cq];
    }
#pragma unroll
    for (int i = 0; i < 4; i++) {
        int idx = t + i * 256;
        int rr = idx >> 4, cq = (idx & 15) * 4;
        int c = cb * 64 + rr;
        float4 v = make_float4(0.f, 0.f, 0.f, 0.f);
        if (c < CC) v = *(const float4*)&wf[(size_t)c * KF + k0 + cq];
        sw[rr][cq] = v.x; sw[rr][cq + 1] = v.y;
        sw[rr][cq + 2] = v.z; sw[rr][cq + 3] = v.w;
    }
    __syncthreads();
#pragma unroll
    for (int kk = 0; kk < 64; kk++) {
        float a0 = sh[2 * bt][kk], a1 = sh[2 * bt + 1][kk];
#pragma unroll
        for (int j = 0; j < 4; j++) {
            float wv = sw[ct + 16 * j][kk];
            acc[0][j] = fmaf(a0, wv, acc[0][j]);
            acc[1][j] = fmaf(a1, wv, acc[1][j]);
        }
    }
#pragma unroll
    for (int i = 0; i < 2; i++)
#pragma unroll
        for (int j = 0; j < 4; j++) {
            int c = cb * 64 + ct + 16 * j;
            if (c < CC)
                g_fcp[(kz * BB + 2 * bt + i) * CC + c] = acc[i][j];
        }
}

// Kernel 4b: deterministic reduce + bias
__global__ __launch_bounds__(256) void k_fcred(const float* __restrict__ bf,
                                               float* __restrict__ out) {
    int i = blockIdx.x * 256 + threadIdx.x;
    if (i >= BB * CC) return;
    int c = i % CC;
    float s = bf[c];
#pragma unroll
    for (int z = 0; z < KSPLIT; z++) s += g_fcp[z * (BB * CC) + i];
    out[i] = s;
}

extern "C" void kernel_launch(void* const* d_in, const int* in_sizes, int n_in,
                              void* d_out, int out_size) {
    (void)in_sizes; (void)n_in; (void)out_size;
    const int*   x   = (const int*)d_in[0];
    const float* emb = (const float*)d_in[1];
    const float* w1  = (const float*)d_in[2];
    const float* b1  = (const float*)d_in[3];
    const float* w2  = (const float*)d_in[4];
    const float* b2  = (const float*)d_in[5];
    const float* wf  = (const float*)d_in[6];
    const float* bf  = (const float*)d_in[7];
    float* out = (float*)d_out;

    k_gather<<<dim3(32, 32), 256>>>(x, emb);
    k_conv1<<<dim3(128, 32), 192>>>(w1, b1);
    k_conv2<<<dim3(64, 32), 448>>>(w2, b2);
    k_fcp<<<dim3(16, KSPLIT), 256>>>(wf);
    k_fcred<<<125, 256>>>(bf, out);
}